// round 1
// baseline (speedup 1.0000x reference)
#include <cuda_runtime.h>
#include <math.h>

#define BS   128
#define SEQ  128
#define CCH  6
#define LL   20
#define NROWS (BS*SEQ)      // 16384
#define DD   64
#define HH   256
#define MAL  10
#define WTOT 1280           // MAL*SEQ
#define KSEL 3276           // int(16384*0.2)
#define AMAX 18432

// ---------------- scratch (device globals; no runtime alloc allowed) ----------
__device__ float    g_bridge[NROWS*DD];          // 4 MB
__device__ float    g_loss[NROWS];
__device__ unsigned g_scores[NROWS];             // float bits (non-negative -> uint order)
__device__ unsigned g_cutoff_bits;
__device__ int      g_counts[BS];
__device__ int      g_desc[AMAX*3];              // (b, start, end) per atom
__device__ int      g_total;
__device__ float    g_af[(size_t)AMAX*640];      // atom_features (A,64,10)
__device__ float    g_hd[(size_t)AMAX*256];      // hidden for atom_gen gemm

// =========================== K1: CNN encoder + bridge ========================
// 4 rows per block, 128 threads. Weights staged in shared.
__global__ __launch_bounds__(128) void k_encoder(
    const float* __restrict__ x,
    const float* __restrict__ c1w, const float* __restrict__ c1b,
    const float* __restrict__ c2w, const float* __restrict__ c2b,
    const float* __restrict__ c3w, const float* __restrict__ c3b,
    const float* __restrict__ brw, const float* __restrict__ brb,
    float* __restrict__ o_bresh, float* __restrict__ o_fin)
{
    __shared__ float s_c1w[288], s_c1b[16], s_c2w[1536], s_c2b[32];
    __shared__ float s_c3w[3072], s_c3b[32], s_brw[4096], s_brb[64];
    __shared__ float sx[120], sh1[320], sp1[160], sh2[320], sp2[160], sh3[160], sp3[64];
    int tid = threadIdx.x;
    for (int i = tid; i < 288;  i += 128) s_c1w[i] = c1w[i];
    for (int i = tid; i < 16;   i += 128) s_c1b[i] = c1b[i];
    for (int i = tid; i < 1536; i += 128) s_c2w[i] = c2w[i];
    for (int i = tid; i < 32;   i += 128) s_c2b[i] = c2b[i];
    for (int i = tid; i < 3072; i += 128) s_c3w[i] = c3w[i];
    for (int i = tid; i < 32;   i += 128) s_c3b[i] = c3b[i];
    for (int i = tid; i < 4096; i += 128) s_brw[i] = brw[i];
    for (int i = tid; i < 64;   i += 128) s_brb[i] = brb[i];
    __syncthreads();

    for (int r = 0; r < 4; r++) {
        int n = blockIdx.x * 4 + r;
        for (int i = tid; i < 120; i += 128) sx[i] = x[(size_t)n*120 + i];
        __syncthreads();
        // conv1: 16 x 20 (in 6, k3 pad1), relu
        for (int i = tid; i < 320; i += 128) {
            int oc = i / 20, p = i % 20;
            float v = s_c1b[oc];
            #pragma unroll
            for (int ic = 0; ic < 6; ic++) {
                const float* w = &s_c1w[(oc*6+ic)*3];
                const float* xr = &sx[ic*20];
                if (p > 0)  v += w[0]*xr[p-1];
                v += w[1]*xr[p];
                if (p < 19) v += w[2]*xr[p+1];
            }
            sh1[i] = fmaxf(v, 0.f);
        }
        __syncthreads();
        for (int i = tid; i < 160; i += 128) { int oc=i/10, p=i%10; sp1[i] = fmaxf(sh1[oc*20+2*p], sh1[oc*20+2*p+1]); }
        __syncthreads();
        // conv2: 32 x 10 (in 16)
        for (int i = tid; i < 320; i += 128) {
            int oc = i / 10, p = i % 10;
            float v = s_c2b[oc];
            #pragma unroll
            for (int ic = 0; ic < 16; ic++) {
                const float* w = &s_c2w[(oc*16+ic)*3];
                const float* xr = &sp1[ic*10];
                if (p > 0) v += w[0]*xr[p-1];
                v += w[1]*xr[p];
                if (p < 9) v += w[2]*xr[p+1];
            }
            sh2[i] = fmaxf(v, 0.f);
        }
        __syncthreads();
        for (int i = tid; i < 160; i += 128) { int oc=i/5, p=i%5; sp2[i] = fmaxf(sh2[oc*10+2*p], sh2[oc*10+2*p+1]); }
        __syncthreads();
        // conv3: 32 x 5 (in 32)
        for (int i = tid; i < 160; i += 128) {
            int oc = i / 5, p = i % 5;
            float v = s_c3b[oc];
            #pragma unroll
            for (int ic = 0; ic < 32; ic++) {
                const float* w = &s_c3w[(oc*32+ic)*3];
                const float* xr = &sp2[ic*5];
                if (p > 0) v += w[0]*xr[p-1];
                v += w[1]*xr[p];
                if (p < 4) v += w[2]*xr[p+1];
            }
            sh3[i] = fmaxf(v, 0.f);
        }
        __syncthreads();
        for (int i = tid; i < 64; i += 128) { int oc=i/2, p=i%2; sp3[i] = fmaxf(sh3[oc*5+2*p], sh3[oc*5+2*p+1]); }
        __syncthreads();
        // bridge: 64x64 + sigmoid
        if (tid < 64) {
            float v = s_brb[tid];
            #pragma unroll
            for (int i2 = 0; i2 < 64; i2++) v += sp3[i2] * s_brw[i2*64 + tid];
            v = 1.f / (1.f + expf(-v));
            g_bridge[(size_t)n*64 + tid] = v;
            o_bresh[(size_t)n*64 + tid] = v;
            o_fin  [(size_t)n*64 + tid] = v;
        }
        __syncthreads();
    }
}

// ============================ K2: forecast MLP + loss ========================
// 16 rows/block, 256 threads.
__global__ __launch_bounds__(256) void k_forecast(
    const float* __restrict__ f1w, const float* __restrict__ f1b,
    const float* __restrict__ f2w, const float* __restrict__ f2b,
    const float* __restrict__ imu_mask,
    float* __restrict__ o_fo, float* __restrict__ o_fm, float* __restrict__ o_loss)
{
    __shared__ float shft[16*64];
    __shared__ float feat[16*256];
    __shared__ float fo[16*64];
    __shared__ float rmask[16];
    int tid = threadIdx.x;
    int n0 = blockIdx.x * 16;

    for (int i = tid; i < 1024; i += 256) {
        int r = i / 64, d = i % 64;
        int n = n0 + r, t = n % SEQ;
        shft[i] = (t == 0) ? 0.f : g_bridge[((size_t)n - 1)*64 + d];
    }
    if (tid < 16) {
        int n = n0 + tid, t = n % SEQ;
        rmask[tid] = (t == 0) ? 0.f : imu_mask[(size_t)n*120];
    }
    __syncthreads();

    // feat[r][j], j = tid  (relu(shft @ f1w + f1b))
    {
        float acc[16];
        float b = f1b[tid];
        #pragma unroll
        for (int r = 0; r < 16; r++) acc[r] = b;
        for (int i = 0; i < 64; i++) {
            float wv = f1w[i*256 + tid];
            #pragma unroll
            for (int r = 0; r < 16; r++) acc[r] += shft[r*64 + i] * wv;
        }
        #pragma unroll
        for (int r = 0; r < 16; r++) feat[r*256 + tid] = fmaxf(acc[r], 0.f);
    }
    __syncthreads();

    // forcast = feat @ f2w + f2b
    {
        int col = tid & 63, rg = tid >> 6; // 4 row-groups x 4 rows
        float acc[4];
        float b = f2b[col];
        #pragma unroll
        for (int u = 0; u < 4; u++) acc[u] = b;
        for (int i = 0; i < 256; i++) {
            float wv = f2w[i*64 + col];
            #pragma unroll
            for (int u = 0; u < 4; u++) acc[u] += feat[(rg*4+u)*256 + i] * wv;
        }
        #pragma unroll
        for (int u = 0; u < 4; u++) {
            int r = rg*4 + u;
            fo[r*64 + col] = acc[u];
            o_fo[((size_t)(n0 + r))*64 + col] = acc[u];
            o_fm[((size_t)(n0 + r))*64 + col] = rmask[r];
        }
    }
    __syncthreads();

    if (tid < 16) {
        int n = n0 + tid;
        float m = rmask[tid];
        float s = 0.f;
        for (int d = 0; d < 64; d++) {
            float df = (fo[tid*64 + d] - g_bridge[(size_t)n*64 + d]) * m;
            s += df * df;
        }
        float loss = s / 64.f;
        g_loss[n] = loss;
        o_loss[n] = loss;
        g_scores[n] = __float_as_uint(loss * m);
    }
}

// ==================== K3: exact k-th largest (radix select) ==================
__global__ __launch_bounds__(1024) void k_select()
{
    __shared__ unsigned hist[256];
    __shared__ unsigned sprefix;
    __shared__ int srem;
    int tid = threadIdx.x;
    if (tid == 0) { sprefix = 0u; srem = KSEL; }
    __syncthreads();
    for (int pass = 0; pass < 4; pass++) {
        int shift = 24 - pass * 8;
        if (tid < 256) hist[tid] = 0;
        __syncthreads();
        unsigned pref = sprefix;
        unsigned mask = (pass == 0) ? 0u : (0xFFFFFFFFu << (shift + 8));
        for (int i = tid; i < NROWS; i += 1024) {
            unsigned v = g_scores[i];
            if ((v & mask) == pref) atomicAdd(&hist[(v >> shift) & 255], 1u);
        }
        __syncthreads();
        if (tid == 0) {
            int rem = srem;
            unsigned cum = 0;
            int sel = 0;
            for (int b = 255; b >= 0; b--) {
                if (cum + hist[b] >= (unsigned)rem) { sel = b; srem = rem - (int)cum; break; }
                cum += hist[b];
            }
            sprefix = pref | ((unsigned)sel << shift);
        }
        __syncthreads();
    }
    if (tid == 0) g_cutoff_bits = sprefix;
}

// ============== K4: per-batch segment construction + atom list ===============
__global__ __launch_bounds__(128) void k_segments()
{
    int b = threadIdx.x;
    __shared__ int cnt[128];
    float cutoff = __uint_as_float(g_cutoff_bits);
    int segs[160];
    int ns = 0, prev = -1;
    for (int t = 0; t < SEQ; t++) {
        if (g_loss[b*SEQ + t] > cutoff) {
            if (prev >= 0) {
                if (t - prev > MAL) {
                    segs[ns++] = prev;
                    int cur = prev;
                    while (cur < t) { cur += MAL; if (cur >= t) break; segs[ns++] = cur; }
                } else {
                    segs[ns++] = prev;
                }
            }
            prev = t;
        }
    }
    if (prev >= 0) segs[ns++] = prev;
    cnt[b] = ns;
    __syncthreads();
    int off = 0;
    for (int i = 0; i < b; i++) off += cnt[i];
    if (b == 127) {
        int tot = off + ns;
        g_total = tot;
        if (tot == 0) { g_desc[0] = -1; g_desc[1] = 0; g_desc[2] = 0; }
    }
    int last = 0;
    for (int i = 0; i < ns; i++) {
        int e = segs[i];
        g_desc[(off + i)*3 + 0] = b;
        g_desc[(off + i)*3 + 1] = last;
        g_desc[(off + i)*3 + 2] = e;
        last = e;
    }
}

// ========= K5: fill imu_atoms / imu_atoms_mask / atom_features ===============
__global__ __launch_bounds__(256) void k_atoms(
    const float* __restrict__ x, float* __restrict__ o_mask, float* __restrict__ o_atoms)
{
    int g = blockIdx.x;
    int b = g_desc[g*3 + 0], s = g_desc[g*3 + 1], e = g_desc[g*3 + 2];
    int tid = threadIdx.x;
    if (b < 0) {
        for (int i = tid; i < 7680; i += 256) {
            o_mask [(size_t)g*7680 + i] = 0.f;
            o_atoms[(size_t)g*7680 + i] = 0.f;
        }
        for (int i = tid; i < 640; i += 256) g_af[(size_t)g*640 + i] = 0.f;
        return;
    }
    int w = e - s, wL = w * LL, ap = WTOT - wL;
    for (int i = tid; i < 7680; i += 256) {
        int c = i / WTOT, cp = i % WTOT;
        float mv = (cp >= ap) ? 1.f : 0.f;
        int colg = cp - ap;
        float val = 0.f;
        if (colg >= 0) {
            int trow = s + colg / LL, l = colg % LL;
            val = x[(((size_t)b*SEQ + trow)*CCH + c)*LL + l];
        }
        o_mask [(size_t)g*7680 + i] = mv;
        o_atoms[(size_t)g*7680 + i] = val;
    }
    for (int i = tid; i < 640; i += 256) {
        int d = i / 10, t = i % 10;
        int row = e - 10 + t;
        g_af[(size_t)g*640 + i] = (row >= s) ? g_bridge[((size_t)b*SEQ + row)*64 + d] : 0.f;
    }
}

// ===================== K6a: atom encoder -> hd[A][256] =======================
__global__ __launch_bounds__(256) void k_atom_enc(
    const float* __restrict__ ae1w, const float* __restrict__ ae1b,
    const float* __restrict__ ae2w, const float* __restrict__ ae2b,
    const float* __restrict__ ae3w, const float* __restrict__ ae3b,
    const float* __restrict__ ad1w, const float* __restrict__ ad1b)
{
    __shared__ float saf[640], sw1[6144], sh1[320], sp1[160], sh2[80], semb[32];
    int g = blockIdx.x, tid = threadIdx.x;
    for (int i = tid; i < 6144; i += 256) sw1[i] = ae1w[i];
    for (int i = tid; i < 640;  i += 256) saf[i] = g_af[(size_t)g*640 + i];
    __syncthreads();
    // ae1: 32 x 10 over 64 in-ch, relu
    for (int i = tid; i < 320; i += 256) {
        int oc = i / 10, p = i % 10;
        float v = ae1b[oc];
        const float* wb = &sw1[oc*64*3];
        for (int ic = 0; ic < 64; ic++) {
            const float* w = &wb[ic*3];
            const float* xr = &saf[ic*10];
            if (p > 0) v += w[0]*xr[p-1];
            v += w[1]*xr[p];
            if (p < 9) v += w[2]*xr[p+1];
        }
        sh1[i] = fmaxf(v, 0.f);
    }
    __syncthreads();
    for (int i = tid; i < 160; i += 256) { int oc=i/5, p=i%5; sp1[i] = fmaxf(sh1[oc*10+2*p], sh1[oc*10+2*p+1]); }
    __syncthreads();
    // ae2: 16 x 5 over 32 in-ch, relu
    for (int i = tid; i < 80; i += 256) {
        int oc = i / 5, p = i % 5;
        float v = ae2b[oc];
        #pragma unroll
        for (int ic = 0; ic < 32; ic++) {
            const float* w = &ae2w[(oc*32+ic)*3];
            const float* xr = &sp1[ic*5];
            if (p > 0) v += w[0]*xr[p-1];
            v += w[1]*xr[p];
            if (p < 4) v += w[2]*xr[p+1];
        }
        sh2[i] = fmaxf(v, 0.f);
    }
    __syncthreads();
    // emb = h2(80) @ ae3w(80x32) + b
    for (int i = tid; i < 32; i += 256) {
        float v = ae3b[i];
        for (int j = 0; j < 80; j++) v += sh2[j] * ae3w[j*32 + i];
        semb[i] = v;
    }
    __syncthreads();
    // hd = relu(emb(32) @ ad1w(32x256) + b)
    if (tid < 256) {
        float v = ad1b[tid];
        #pragma unroll
        for (int j = 0; j < 32; j++) v += semb[j] * ad1w[j*256 + tid];
        g_hd[(size_t)g*256 + tid] = fmaxf(v, 0.f);
    }
}

// =========== K6b: atom_gen GEMM  (A x 256) @ (256 x 7680) + bias =============
__global__ __launch_bounds__(256) void k_gemm_atomgen(
    const float* __restrict__ Bw, const float* __restrict__ bias,
    float* __restrict__ Cout, int M)
{
    __shared__ float As[16][64];
    __shared__ float Bs[16][64];
    int bx = blockIdx.x;   // N tiles: 120
    int by = blockIdx.y;   // M tiles
    int tx = threadIdx.x % 16, ty = threadIdx.x / 16;
    int row0 = by * 64, col0 = bx * 64;
    float acc[4][4] = {};
    for (int kc = 0; kc < 256; kc += 16) {
        for (int i = threadIdx.x; i < 1024; i += 256) {
            int r = i / 16, kk = i % 16;
            int gr = row0 + r;
            As[kk][r] = (gr < M) ? g_hd[(size_t)gr*256 + kc + kk] : 0.f;
        }
        for (int i = threadIdx.x; i < 1024; i += 256) {
            int kk = i / 64, c = i % 64;
            Bs[kk][c] = Bw[(size_t)(kc + kk)*7680 + col0 + c];
        }
        __syncthreads();
        #pragma unroll
        for (int kk = 0; kk < 16; kk++) {
            float a[4], b[4];
            #pragma unroll
            for (int u = 0; u < 4; u++) { a[u] = As[kk][ty*4 + u]; b[u] = Bs[kk][tx*4 + u]; }
            #pragma unroll
            for (int u = 0; u < 4; u++)
                #pragma unroll
                for (int v = 0; v < 4; v++) acc[u][v] += a[u] * b[v];
        }
        __syncthreads();
    }
    #pragma unroll
    for (int u = 0; u < 4; u++) {
        int gr = row0 + ty*4 + u;
        if (gr < M) {
            #pragma unroll
            for (int v = 0; v < 4; v++) {
                int gc = col0 + tx*4 + v;
                Cout[(size_t)gr*7680 + gc] = acc[u][v] + bias[gc];
            }
        }
    }
}

// ============================ K7: decoder -> imu_gen =========================
// 8 rows/block, 256 threads
__global__ __launch_bounds__(256) void k_decoder(
    const float* __restrict__ d1w, const float* __restrict__ d1b,
    const float* __restrict__ d2w, const float* __restrict__ d2b,
    float* __restrict__ o_imu)
{
    __shared__ float s_d1w[2560], s_d1b[32], s_d2w[576], s_d2b[6];
    __shared__ float br[8*64], gbuf[8*640];
    int tid = threadIdx.x;
    int n0 = blockIdx.x * 8;
    for (int i = tid; i < 2560; i += 256) s_d1w[i] = d1w[i];
    for (int i = tid; i < 32;   i += 256) s_d1b[i] = d1b[i];
    for (int i = tid; i < 576;  i += 256) s_d2w[i] = d2w[i];
    for (int i = tid; i < 6;    i += 256) s_d2b[i] = d2b[i];
    for (int i = tid; i < 512;  i += 256) {
        int r = i / 64, d = i % 64;
        br[i] = g_bridge[((size_t)(n0 + r))*64 + d];
    }
    __syncthreads();
    // g[n,o,i,k] = sum_c br[n,c*4+i]*d1w[(c*32+o)*5+k]; relu(+d1b[o]); flat (o*20 + i*5 + k)
    for (int i = tid; i < 8*640; i += 256) {
        int r = i / 640, j = i % 640;
        int o = j / 20, rest = j % 20, ii = rest / 5, kk = rest % 5;
        float v = 0.f;
        #pragma unroll
        for (int c = 0; c < 16; c++) v += br[r*64 + c*4 + ii] * s_d1w[(c*32 + o)*5 + kk];
        gbuf[r*640 + j] = fmaxf(v + s_d1b[o], 0.f);
    }
    __syncthreads();
    // conv d2: 6 x 20 over 32 in-ch (no relu)
    for (int i = tid; i < 8*120; i += 256) {
        int r = i / 120, j = i % 120;
        int co = j / 20, l = j % 20;
        float v = s_d2b[co];
        #pragma unroll
        for (int ci = 0; ci < 32; ci++) {
            const float* w = &s_d2w[(co*32 + ci)*3];
            const float* xr = &gbuf[r*640 + ci*20];
            if (l > 0)  v += w[0]*xr[l-1];
            v += w[1]*xr[l];
            if (l < 19) v += w[2]*xr[l+1];
        }
        o_imu[((size_t)(n0 + r))*120 + j] = v;
    }
}

// ================================= launch ====================================
extern "C" void kernel_launch(void* const* d_in, const int* in_sizes, int n_in,
                              void* d_out, int out_size)
{
    const float* x        = (const float*)d_in[0];
    const float* imu_mask = (const float*)d_in[1];
    // d_in[2] imu_len: unused by reference
    const float* c1w = (const float*)d_in[3];
    const float* c1b = (const float*)d_in[4];
    const float* c2w = (const float*)d_in[5];
    const float* c2b = (const float*)d_in[6];
    const float* c3w = (const float*)d_in[7];
    const float* c3b = (const float*)d_in[8];
    const float* brw = (const float*)d_in[9];
    const float* brb = (const float*)d_in[10];
    const float* f1w = (const float*)d_in[11];
    const float* f1b = (const float*)d_in[12];
    const float* f2w = (const float*)d_in[13];
    const float* f2b = (const float*)d_in[14];
    const float* d1w = (const float*)d_in[15];
    const float* d1b = (const float*)d_in[16];
    const float* d2w = (const float*)d_in[17];
    const float* d2b = (const float*)d_in[18];
    const float* ae1w = (const float*)d_in[19];
    const float* ae1b = (const float*)d_in[20];
    const float* ae2w = (const float*)d_in[21];
    const float* ae2b = (const float*)d_in[22];
    const float* ae3w = (const float*)d_in[23];
    const float* ae3b = (const float*)d_in[24];
    const float* ad1w = (const float*)d_in[25];
    const float* ad1b = (const float*)d_in[26];
    const float* ad2w = (const float*)d_in[27];
    const float* ad2b = (const float*)d_in[28];
    (void)in_sizes; (void)n_in;

    float* out = (float*)d_out;
    long long A = ((long long)out_size - 6176768LL) / 23040LL;
    if (A < 1) A = 1;
    if (A > AMAX) A = AMAX;

    float* o_imu   = out;                          // (bs,seq,6,20)  1,966,080
    float* o_ag    = o_imu   + 1966080;            // (A,6,1280)
    float* o_mask  = o_ag    + (size_t)A*7680;     // (A,6,1280)
    float* o_atoms = o_mask  + (size_t)A*7680;     // (A,6,1280)
    float* o_bresh = o_atoms + (size_t)A*7680;     // (N,16,4) == bridge_out
    float* o_fin   = o_bresh + 1048576;            // (N,64)   == bridge_out
    float* o_fo    = o_fin   + 1048576;            // (N,64)
    float* o_fm    = o_fo    + 1048576;            // (N,64)
    float* o_loss  = o_fm    + 1048576;            // (N,)

    k_encoder<<<NROWS/4, 128>>>(x, c1w, c1b, c2w, c2b, c3w, c3b, brw, brb, o_bresh, o_fin);
    k_forecast<<<NROWS/16, 256>>>(f1w, f1b, f2w, f2b, imu_mask, o_fo, o_fm, o_loss);
    k_select<<<1, 1024>>>();
    k_segments<<<1, 128>>>();
    k_atoms<<<(unsigned)A, 256>>>(x, o_mask, o_atoms);
    k_atom_enc<<<(unsigned)A, 256>>>(ae1w, ae1b, ae2w, ae2b, ae3w, ae3b, ad1w, ad1b);
    dim3 gg(7680/64, (unsigned)((A + 63) / 64));
    k_gemm_atomgen<<<gg, 256>>>(ad2w, ad2b, o_ag, (int)A);
    k_decoder<<<NROWS/8, 256>>>(d1w, d1b, d2w, d2b, o_imu);
}

// round 2
// speedup vs baseline: 1.3559x; 1.3559x over previous
#include <cuda_runtime.h>
#include <cuda_bf16.h>
#include <math.h>

#define BS   128
#define SEQ  128
#define CCH  6
#define LL   20
#define NROWS (BS*SEQ)      // 16384
#define DD   64
#define HH   256
#define MAL  10
#define WTOT 1280           // MAL*SEQ
#define KSEL 3276           // int(16384*0.2)
#define AMAX 18432

// ---------------- scratch (device globals; no runtime alloc allowed) ----------
__device__ float    g_bridge[NROWS*DD];          // 4 MB
__device__ float    g_lossT[NROWS];              // transposed [t][b] for coalesced scan
__device__ unsigned g_scores[NROWS];             // float bits (non-negative -> uint order)
__device__ int      g_desc[AMAX*3];              // (b, start, end) per atom
__device__ int      g_total;
__device__ float    g_af[(size_t)AMAX*640];      // atom_features (A,64,10)
__device__ float    g_hd[(size_t)AMAX*256];      // hidden for atom_gen gemm

// =========================== K1: CNN encoder + bridge ========================
// warp-per-row: 8 warps/block, 8 rows/block, per-warp smem ping-pong buffers.
__global__ __launch_bounds__(256) void k_encoder(
    const float* __restrict__ x,
    const float* __restrict__ c1w, const float* __restrict__ c1b,
    const float* __restrict__ c2w, const float* __restrict__ c2b,
    const float* __restrict__ c3w, const float* __restrict__ c3b,
    const float* __restrict__ brw, const float* __restrict__ brb,
    float* __restrict__ o_bresh, float* __restrict__ o_fin)
{
    __shared__ float s_c1w[288], s_c1b[16], s_c2w[1536], s_c2b[32];
    __shared__ float s_c3w[3072], s_c3b[32], s_brb[64];
    __shared__ float bufA[8][320], bufB[8][320];
    int tid = threadIdx.x;
    for (int i = tid; i < 288;  i += 256) s_c1w[i] = c1w[i];
    for (int i = tid; i < 16;   i += 256) s_c1b[i] = c1b[i];
    for (int i = tid; i < 1536; i += 256) s_c2w[i] = c2w[i];
    for (int i = tid; i < 32;   i += 256) s_c2b[i] = c2b[i];
    for (int i = tid; i < 3072; i += 256) s_c3w[i] = c3w[i];
    for (int i = tid; i < 32;   i += 256) s_c3b[i] = c3b[i];
    for (int i = tid; i < 64;   i += 256) s_brb[i] = brb[i];
    __syncthreads();

    int w = tid >> 5, l = tid & 31;
    int n = blockIdx.x * 8 + w;
    float* A_ = bufA[w];
    float* B_ = bufB[w];

    // load x row (6ch x 20)
    for (int i = l; i < 120; i += 32) A_[i] = x[(size_t)n*120 + i];
    __syncwarp();
    // conv1: 16 x 20 (in 6, k3 pad1), relu -> B_
    for (int i = l; i < 320; i += 32) {
        int oc = i / 20, p = i % 20;
        float v = s_c1b[oc];
        #pragma unroll
        for (int ic = 0; ic < 6; ic++) {
            const float* wv = &s_c1w[(oc*6+ic)*3];
            const float* xr = &A_[ic*20];
            if (p > 0)  v += wv[0]*xr[p-1];
            v += wv[1]*xr[p];
            if (p < 19) v += wv[2]*xr[p+1];
        }
        B_[i] = fmaxf(v, 0.f);
    }
    __syncwarp();
    // pool1 -> A_ (16ch x 10)
    for (int i = l; i < 160; i += 32) { int oc=i/10, p=i%10; A_[i] = fmaxf(B_[oc*20+2*p], B_[oc*20+2*p+1]); }
    __syncwarp();
    // conv2: 32 x 10 (in 16) -> B_
    for (int i = l; i < 320; i += 32) {
        int oc = i / 10, p = i % 10;
        float v = s_c2b[oc];
        #pragma unroll
        for (int ic = 0; ic < 16; ic++) {
            const float* wv = &s_c2w[(oc*16+ic)*3];
            const float* xr = &A_[ic*10];
            if (p > 0) v += wv[0]*xr[p-1];
            v += wv[1]*xr[p];
            if (p < 9) v += wv[2]*xr[p+1];
        }
        B_[i] = fmaxf(v, 0.f);
    }
    __syncwarp();
    // pool2 -> A_ (32ch x 5)
    for (int i = l; i < 160; i += 32) { int oc=i/5, p=i%5; A_[i] = fmaxf(B_[oc*10+2*p], B_[oc*10+2*p+1]); }
    __syncwarp();
    // conv3: 32 x 5 (in 32) -> B_
    for (int i = l; i < 160; i += 32) {
        int oc = i / 5, p = i % 5;
        float v = s_c3b[oc];
        #pragma unroll
        for (int ic = 0; ic < 32; ic++) {
            const float* wv = &s_c3w[(oc*32+ic)*3];
            const float* xr = &A_[ic*5];
            if (p > 0) v += wv[0]*xr[p-1];
            v += wv[1]*xr[p];
            if (p < 4) v += wv[2]*xr[p+1];
        }
        B_[i] = fmaxf(v, 0.f);
    }
    __syncwarp();
    // pool3 -> A_ (64)
    for (int i = l; i < 64; i += 32) { int oc=i/2, p=i%2; A_[i] = fmaxf(B_[oc*5+2*p], B_[oc*5+2*p+1]); }
    __syncwarp();
    // bridge: 64x64 + sigmoid; 2 cols/lane (brw via L1)
    #pragma unroll
    for (int cc = 0; cc < 2; cc++) {
        int c = l + cc*32;
        float v = s_brb[c];
        #pragma unroll 8
        for (int i2 = 0; i2 < 64; i2++) v += A_[i2] * __ldg(&brw[i2*64 + c]);
        v = 1.f / (1.f + expf(-v));
        g_bridge[(size_t)n*64 + c] = v;
        o_bresh [(size_t)n*64 + c] = v;
        o_fin   [(size_t)n*64 + c] = v;
    }
}

// ============================ K2: forecast MLP + loss ========================
// 16 rows/block, 256 threads.
__global__ __launch_bounds__(256) void k_forecast(
    const float* __restrict__ f1w, const float* __restrict__ f1b,
    const float* __restrict__ f2w, const float* __restrict__ f2b,
    const float* __restrict__ imu_mask,
    float* __restrict__ o_fo, float* __restrict__ o_fm, float* __restrict__ o_loss)
{
    __shared__ float shft[16*64];
    __shared__ float feat[16*256];
    __shared__ float fo[16*64];
    __shared__ float rmask[16];
    int tid = threadIdx.x;
    int n0 = blockIdx.x * 16;

    for (int i = tid; i < 1024; i += 256) {
        int r = i / 64, d = i % 64;
        int n = n0 + r, t = n % SEQ;
        shft[i] = (t == 0) ? 0.f : g_bridge[((size_t)n - 1)*64 + d];
    }
    if (tid < 16) {
        int n = n0 + tid, t = n % SEQ;
        rmask[tid] = (t == 0) ? 0.f : imu_mask[(size_t)n*120];
    }
    __syncthreads();

    // feat[r][j], j = tid  (relu(shft @ f1w + f1b))
    {
        float acc[16];
        float b = f1b[tid];
        #pragma unroll
        for (int r = 0; r < 16; r++) acc[r] = b;
        for (int i = 0; i < 64; i++) {
            float wv = f1w[i*256 + tid];
            #pragma unroll
            for (int r = 0; r < 16; r++) acc[r] += shft[r*64 + i] * wv;
        }
        #pragma unroll
        for (int r = 0; r < 16; r++) feat[r*256 + tid] = fmaxf(acc[r], 0.f);
    }
    __syncthreads();

    // forcast = feat @ f2w + f2b
    {
        int col = tid & 63, rg = tid >> 6; // 4 row-groups x 4 rows
        float acc[4];
        float b = f2b[col];
        #pragma unroll
        for (int u = 0; u < 4; u++) acc[u] = b;
        for (int i = 0; i < 256; i++) {
            float wv = f2w[i*64 + col];
            #pragma unroll
            for (int u = 0; u < 4; u++) acc[u] += feat[(rg*4+u)*256 + i] * wv;
        }
        #pragma unroll
        for (int u = 0; u < 4; u++) {
            int r = rg*4 + u;
            fo[r*64 + col] = acc[u];
            o_fo[((size_t)(n0 + r))*64 + col] = acc[u];
            o_fm[((size_t)(n0 + r))*64 + col] = rmask[r];
        }
    }
    __syncthreads();

    if (tid < 16) {
        int n = n0 + tid;
        float m = rmask[tid];
        float s = 0.f;
        for (int d = 0; d < 64; d++) {
            float df = (fo[tid*64 + d] - g_bridge[(size_t)n*64 + d]) * m;
            s += df * df;
        }
        float loss = s / 64.f;
        o_loss[n] = loss;
        g_lossT[(n & 127)*BS + (n >> 7)] = loss;
        g_scores[n] = __float_as_uint(loss * m);
    }
}

// ======= K3: fused exact k-th largest (radix select) + segment build =========
__global__ __launch_bounds__(1024) void k_selectseg()
{
    __shared__ unsigned hist[256];
    __shared__ unsigned sprefix;
    __shared__ int srem;
    __shared__ int cnt[128];
    int tid = threadIdx.x;
    if (tid == 0) { sprefix = 0u; srem = KSEL; }
    __syncthreads();
    for (int pass = 0; pass < 4; pass++) {
        int shift = 24 - pass * 8;
        if (tid < 256) hist[tid] = 0;
        __syncthreads();
        unsigned pref = sprefix;
        unsigned mask = (pass == 0) ? 0u : (0xFFFFFFFFu << (shift + 8));
        for (int i = tid; i < NROWS; i += 1024) {
            unsigned v = g_scores[i];
            if ((v & mask) == pref) atomicAdd(&hist[(v >> shift) & 255], 1u);
        }
        __syncthreads();
        if (tid == 0) {
            int rem = srem;
            unsigned cum = 0;
            int sel = 0;
            for (int b = 255; b >= 0; b--) {
                if (cum + hist[b] >= (unsigned)rem) { sel = b; srem = rem - (int)cum; break; }
                cum += hist[b];
            }
            sprefix = pref | ((unsigned)sel << shift);
        }
        __syncthreads();
    }
    float cutoff = __uint_as_float(sprefix);

    // per-batch segment construction (threads 0..127, coalesced reads of g_lossT)
    int segs[160];
    int ns = 0;
    if (tid < 128) {
        int b = tid, prev = -1;
        for (int t = 0; t < SEQ; t++) {
            float lv = g_lossT[t*BS + b];
            if (lv > cutoff) {
                if (prev >= 0) {
                    if (t - prev > MAL) {
                        segs[ns++] = prev;
                        int cur = prev;
                        while (cur < t) { cur += MAL; if (cur >= t) break; segs[ns++] = cur; }
                    } else {
                        segs[ns++] = prev;
                    }
                }
                prev = t;
            }
        }
        if (prev >= 0) segs[ns++] = prev;
        cnt[b] = ns;
    }
    __syncthreads();
    if (tid < 128) {
        int off = 0;
        for (int i = 0; i < tid; i++) off += cnt[i];
        if (tid == 127) {
            int tot = off + ns;
            g_total = tot;
            if (tot == 0) { g_desc[0] = -1; g_desc[1] = 0; g_desc[2] = 0; }
        }
        int last = 0;
        for (int i = 0; i < ns; i++) {
            int e = segs[i];
            g_desc[(off + i)*3 + 0] = tid;
            g_desc[(off + i)*3 + 1] = last;
            g_desc[(off + i)*3 + 2] = e;
            last = e;
        }
    }
}

// ========= K5: fill imu_atoms / imu_atoms_mask / atom_features ===============
__global__ __launch_bounds__(256) void k_atoms(
    const float* __restrict__ x, float* __restrict__ o_mask, float* __restrict__ o_atoms)
{
    int g = blockIdx.x;
    int b = g_desc[g*3 + 0], s = g_desc[g*3 + 1], e = g_desc[g*3 + 2];
    int tid = threadIdx.x;
    if (b < 0) {
        for (int i = tid; i < 7680; i += 256) {
            o_mask [(size_t)g*7680 + i] = 0.f;
            o_atoms[(size_t)g*7680 + i] = 0.f;
        }
        for (int i = tid; i < 640; i += 256) g_af[(size_t)g*640 + i] = 0.f;
        return;
    }
    int w = e - s, wL = w * LL, ap = WTOT - wL;
    for (int i = tid; i < 7680; i += 256) {
        int c = i / WTOT, cp = i % WTOT;
        float mv = (cp >= ap) ? 1.f : 0.f;
        int colg = cp - ap;
        float val = 0.f;
        if (colg >= 0) {
            int trow = s + colg / LL, ll = colg % LL;
            val = x[(((size_t)b*SEQ + trow)*CCH + c)*LL + ll];
        }
        o_mask [(size_t)g*7680 + i] = mv;
        o_atoms[(size_t)g*7680 + i] = val;
    }
    for (int i = tid; i < 640; i += 256) {
        int d = i / 10, t = i % 10;
        int row = e - 10 + t;
        g_af[(size_t)g*640 + i] = (row >= s) ? g_bridge[((size_t)b*SEQ + row)*64 + d] : 0.f;
    }
}

// ===================== K6a: atom encoder -> hd[A][256] =======================
__global__ __launch_bounds__(256) void k_atom_enc(
    const float* __restrict__ ae1w, const float* __restrict__ ae1b,
    const float* __restrict__ ae2w, const float* __restrict__ ae2b,
    const float* __restrict__ ae3w, const float* __restrict__ ae3b,
    const float* __restrict__ ad1w, const float* __restrict__ ad1b)
{
    __shared__ float saf[640], sw1[6144], sh1[320], sp1[160], sh2[80], semb[32];
    int g = blockIdx.x, tid = threadIdx.x;
    for (int i = tid; i < 6144; i += 256) sw1[i] = ae1w[i];
    for (int i = tid; i < 640;  i += 256) saf[i] = g_af[(size_t)g*640 + i];
    __syncthreads();
    // ae1: 32 x 10 over 64 in-ch, relu
    for (int i = tid; i < 320; i += 256) {
        int oc = i / 10, p = i % 10;
        float v = ae1b[oc];
        const float* wb = &sw1[oc*64*3];
        for (int ic = 0; ic < 64; ic++) {
            const float* wv = &wb[ic*3];
            const float* xr = &saf[ic*10];
            if (p > 0) v += wv[0]*xr[p-1];
            v += wv[1]*xr[p];
            if (p < 9) v += wv[2]*xr[p+1];
        }
        sh1[i] = fmaxf(v, 0.f);
    }
    __syncthreads();
    for (int i = tid; i < 160; i += 256) { int oc=i/5, p=i%5; sp1[i] = fmaxf(sh1[oc*10+2*p], sh1[oc*10+2*p+1]); }
    __syncthreads();
    // ae2: 16 x 5 over 32 in-ch, relu
    for (int i = tid; i < 80; i += 256) {
        int oc = i / 5, p = i % 5;
        float v = ae2b[oc];
        #pragma unroll
        for (int ic = 0; ic < 32; ic++) {
            const float* wv = &ae2w[(oc*32+ic)*3];
            const float* xr = &sp1[ic*5];
            if (p > 0) v += wv[0]*xr[p-1];
            v += wv[1]*xr[p];
            if (p < 4) v += wv[2]*xr[p+1];
        }
        sh2[i] = fmaxf(v, 0.f);
    }
    __syncthreads();
    // emb = h2(80) @ ae3w(80x32) + b
    for (int i = tid; i < 32; i += 256) {
        float v = ae3b[i];
        for (int j = 0; j < 80; j++) v += sh2[j] * ae3w[j*32 + i];
        semb[i] = v;
    }
    __syncthreads();
    // hd = relu(emb(32) @ ad1w(32x256) + b)
    if (tid < 256) {
        float v = ad1b[tid];
        #pragma unroll
        for (int j = 0; j < 32; j++) v += semb[j] * ad1w[j*256 + tid];
        g_hd[(size_t)g*256 + tid] = fmaxf(v, 0.f);
    }
}

// =========== K6b: atom_gen GEMM via bf16-split tensor cores ==================
// C(M x 7680) = hd(M x 256) @ ad2w(256 x 7680) + bias
// 2-term bf16 split: a*b ~= ah*bh + ah*bl + al*bh  (error ~3e-5 rel)
__device__ __forceinline__ unsigned pk2(float v0, float v1, float& r0, float& r1)
{
    __nv_bfloat16 h0 = __float2bfloat16(v0);
    __nv_bfloat16 h1 = __float2bfloat16(v1);
    r0 = v0 - __bfloat162float(h0);
    r1 = v1 - __bfloat162float(h1);
    return (unsigned)__bfloat16_as_ushort(h0) | ((unsigned)__bfloat16_as_ushort(h1) << 16);
}
__device__ __forceinline__ unsigned pklo(float r0, float r1)
{
    __nv_bfloat16 l0 = __float2bfloat16(r0);
    __nv_bfloat16 l1 = __float2bfloat16(r1);
    return (unsigned)__bfloat16_as_ushort(l0) | ((unsigned)__bfloat16_as_ushort(l1) << 16);
}
__device__ __forceinline__ void mma16816(float* c, const unsigned* a, unsigned b0, unsigned b1)
{
    asm volatile(
        "mma.sync.aligned.m16n8k16.row.col.f32.bf16.bf16.f32 "
        "{%0,%1,%2,%3}, {%4,%5,%6,%7}, {%8,%9}, {%0,%1,%2,%3};\n"
        : "+f"(c[0]), "+f"(c[1]), "+f"(c[2]), "+f"(c[3])
        : "r"(a[0]), "r"(a[1]), "r"(a[2]), "r"(a[3]), "r"(b0), "r"(b1));
}

#define ASTR 136
__global__ __launch_bounds__(256) void k_gemm_atomgen(
    const float* __restrict__ Bw, const float* __restrict__ bias,
    float* __restrict__ Cout, int M)
{
    __shared__ unsigned AsH[16][ASTR], AsL[16][ASTR];
    __shared__ unsigned BsH[16][ASTR], BsL[16][ASTR];
    int tid = threadIdx.x;
    int lane = tid & 31, wid = tid >> 5;
    int warp_m = wid & 3, warp_n = wid >> 2;     // 4 x 2 warps; warp tile 32(M) x 64(N)
    int gtop = lane >> 2, tig = lane & 3;
    int row0 = blockIdx.y * 128, col0 = blockIdx.x * 128;

    float acc[2][8][4];
    #pragma unroll
    for (int r = 0; r < 2; r++)
        #pragma unroll
        for (int nt = 0; nt < 8; nt++)
            #pragma unroll
            for (int q = 0; q < 4; q++) acc[r][nt][q] = 0.f;

    for (int k0 = 0; k0 < 256; k0 += 32) {
        // stage A: 128 rows x 16 kp (pairs of k)
        for (int e2 = tid; e2 < 2048; e2 += 256) {
            int kp = e2 >> 7, m = e2 & 127;
            int gr = row0 + m;
            float2 a = (gr < M) ? *(const float2*)&g_hd[(size_t)gr*256 + k0 + 2*kp]
                                : make_float2(0.f, 0.f);
            float r0, r1;
            AsH[kp][m] = pk2(a.x, a.y, r0, r1);
            AsL[kp][m] = pklo(r0, r1);
        }
        // stage B (transpose to [kp][n])
        for (int e2 = tid; e2 < 2048; e2 += 256) {
            int kp = e2 >> 7, nn = e2 & 127;
            float v0 = Bw[(size_t)(k0 + 2*kp    )*7680 + col0 + nn];
            float v1 = Bw[(size_t)(k0 + 2*kp + 1)*7680 + col0 + nn];
            float r0, r1;
            BsH[kp][nn] = pk2(v0, v1, r0, r1);
            BsL[kp][nn] = pklo(r0, r1);
        }
        __syncthreads();
        #pragma unroll
        for (int ks = 0; ks < 2; ks++) {
            unsigned aH[2][4], aL[2][4];
            #pragma unroll
            for (int r = 0; r < 2; r++) {
                int mrow = warp_m*32 + r*16;
                aH[r][0] = AsH[ks*8 + tig    ][mrow + gtop];
                aH[r][1] = AsH[ks*8 + tig    ][mrow + gtop + 8];
                aH[r][2] = AsH[ks*8 + tig + 4][mrow + gtop];
                aH[r][3] = AsH[ks*8 + tig + 4][mrow + gtop + 8];
                aL[r][0] = AsL[ks*8 + tig    ][mrow + gtop];
                aL[r][1] = AsL[ks*8 + tig    ][mrow + gtop + 8];
                aL[r][2] = AsL[ks*8 + tig + 4][mrow + gtop];
                aL[r][3] = AsL[ks*8 + tig + 4][mrow + gtop + 8];
            }
            #pragma unroll
            for (int nt = 0; nt < 8; nt++) {
                int ncol = warp_n*64 + nt*8 + gtop;
                unsigned bH0 = BsH[ks*8 + tig    ][ncol];
                unsigned bH1 = BsH[ks*8 + tig + 4][ncol];
                unsigned bL0 = BsL[ks*8 + tig    ][ncol];
                unsigned bL1 = BsL[ks*8 + tig + 4][ncol];
                #pragma unroll
                for (int r = 0; r < 2; r++) {
                    mma16816(acc[r][nt], aH[r], bH0, bH1);
                    mma16816(acc[r][nt], aH[r], bL0, bL1);
                    mma16816(acc[r][nt], aL[r], bH0, bH1);
                }
            }
        }
        __syncthreads();
    }

    // epilogue: += bias, store
    #pragma unroll
    for (int r = 0; r < 2; r++) {
        int gr0 = row0 + warp_m*32 + r*16 + gtop;
        #pragma unroll
        for (int nt = 0; nt < 8; nt++) {
            int gc = col0 + warp_n*64 + nt*8 + 2*tig;
            float b0 = bias[gc], b1 = bias[gc + 1];
            if (gr0 < M) {
                float2 v = make_float2(acc[r][nt][0] + b0, acc[r][nt][1] + b1);
                *(float2*)&Cout[(size_t)gr0*7680 + gc] = v;
            }
            if (gr0 + 8 < M) {
                float2 v = make_float2(acc[r][nt][2] + b0, acc[r][nt][3] + b1);
                *(float2*)&Cout[(size_t)(gr0 + 8)*7680 + gc] = v;
            }
        }
    }
}

// ============================ K7: decoder -> imu_gen =========================
// 8 rows/block, 256 threads
__global__ __launch_bounds__(256) void k_decoder(
    const float* __restrict__ d1w, const float* __restrict__ d1b,
    const float* __restrict__ d2w, const float* __restrict__ d2b,
    float* __restrict__ o_imu)
{
    __shared__ float s_d1w[2560], s_d1b[32], s_d2w[576], s_d2b[6];
    __shared__ float br[8*64], gbuf[8*640];
    int tid = threadIdx.x;
    int n0 = blockIdx.x * 8;
    for (int i = tid; i < 2560; i += 256) s_d1w[i] = d1w[i];
    for (int i = tid; i < 32;   i += 256) s_d1b[i] = d1b[i];
    for (int i = tid; i < 576;  i += 256) s_d2w[i] = d2w[i];
    for (int i = tid; i < 6;    i += 256) s_d2b[i] = d2b[i];
    for (int i = tid; i < 512;  i += 256) {
        int r = i / 64, d = i % 64;
        br[i] = g_bridge[((size_t)(n0 + r))*64 + d];
    }
    __syncthreads();
    // g[n,o,i,k] = sum_c br[n,c*4+i]*d1w[(c*32+o)*5+k]; relu(+d1b[o]); flat (o*20 + i*5 + k)
    for (int i = tid; i < 8*640; i += 256) {
        int r = i / 640, j = i % 640;
        int o = j / 20, rest = j % 20, ii = rest / 5, kk = rest % 5;
        float v = 0.f;
        #pragma unroll
        for (int c = 0; c < 16; c++) v += br[r*64 + c*4 + ii] * s_d1w[(c*32 + o)*5 + kk];
        gbuf[r*640 + j] = fmaxf(v + s_d1b[o], 0.f);
    }
    __syncthreads();
    // conv d2: 6 x 20 over 32 in-ch (no relu)
    for (int i = tid; i < 8*120; i += 256) {
        int r = i / 120, j = i % 120;
        int co = j / 20, ll = j % 20;
        float v = s_d2b[co];
        #pragma unroll
        for (int ci = 0; ci < 32; ci++) {
            const float* wv = &s_d2w[(co*32 + ci)*3];
            const float* xr = &gbuf[r*640 + ci*20];
            if (ll > 0)  v += wv[0]*xr[ll-1];
            v += wv[1]*xr[ll];
            if (ll < 19) v += wv[2]*xr[ll+1];
        }
        o_imu[((size_t)(n0 + r))*120 + j] = v;
    }
}

// ================================= launch ====================================
extern "C" void kernel_launch(void* const* d_in, const int* in_sizes, int n_in,
                              void* d_out, int out_size)
{
    const float* x        = (const float*)d_in[0];
    const float* imu_mask = (const float*)d_in[1];
    // d_in[2] imu_len: unused by reference
    const float* c1w = (const float*)d_in[3];
    const float* c1b = (const float*)d_in[4];
    const float* c2w = (const float*)d_in[5];
    const float* c2b = (const float*)d_in[6];
    const float* c3w = (const float*)d_in[7];
    const float* c3b = (const float*)d_in[8];
    const float* brw = (const float*)d_in[9];
    const float* brb = (const float*)d_in[10];
    const float* f1w = (const float*)d_in[11];
    const float* f1b = (const float*)d_in[12];
    const float* f2w = (const float*)d_in[13];
    const float* f2b = (const float*)d_in[14];
    const float* d1w = (const float*)d_in[15];
    const float* d1b = (const float*)d_in[16];
    const float* d2w = (const float*)d_in[17];
    const float* d2b = (const float*)d_in[18];
    const float* ae1w = (const float*)d_in[19];
    const float* ae1b = (const float*)d_in[20];
    const float* ae2w = (const float*)d_in[21];
    const float* ae2b = (const float*)d_in[22];
    const float* ae3w = (const float*)d_in[23];
    const float* ae3b = (const float*)d_in[24];
    const float* ad1w = (const float*)d_in[25];
    const float* ad1b = (const float*)d_in[26];
    const float* ad2w = (const float*)d_in[27];
    const float* ad2b = (const float*)d_in[28];
    (void)in_sizes; (void)n_in;

    float* out = (float*)d_out;
    long long A = ((long long)out_size - 6176768LL) / 23040LL;
    if (A < 1) A = 1;
    if (A > AMAX) A = AMAX;

    float* o_imu   = out;                          // (bs,seq,6,20)  1,966,080
    float* o_ag    = o_imu   + 1966080;            // (A,6,1280)
    float* o_mask  = o_ag    + (size_t)A*7680;     // (A,6,1280)
    float* o_atoms = o_mask  + (size_t)A*7680;     // (A,6,1280)
    float* o_bresh = o_atoms + (size_t)A*7680;     // (N,16,4) == bridge_out
    float* o_fin   = o_bresh + 1048576;            // (N,64)   == bridge_out
    float* o_fo    = o_fin   + 1048576;            // (N,64)
    float* o_fm    = o_fo    + 1048576;            // (N,64)
    float* o_loss  = o_fm    + 1048576;            // (N,)

    k_encoder<<<NROWS/8, 256>>>(x, c1w, c1b, c2w, c2b, c3w, c3b, brw, brb, o_bresh, o_fin);
    k_forecast<<<NROWS/16, 256>>>(f1w, f1b, f2w, f2b, imu_mask, o_fo, o_fm, o_loss);
    k_selectseg<<<1, 1024>>>();
    k_atoms<<<(unsigned)A, 256>>>(x, o_mask, o_atoms);
    k_atom_enc<<<(unsigned)A, 256>>>(ae1w, ae1b, ae2w, ae2b, ae3w, ae3b, ad1w, ad1b);
    dim3 gg(7680/128, (unsigned)((A + 127) / 128));
    k_gemm_atomgen<<<gg, 256>>>(ad2w, ad2b, o_ag, (int)A);
    k_decoder<<<NROWS/8, 256>>>(d1w, d1b, d2w, d2b, o_imu);
}